// round 8
// baseline (speedup 1.0000x reference)
#include <cuda_runtime.h>

#define C_S 384
#define C_Z 128
#define MAX_N 2048
#define NSM 148
#define MAIN_BLKS_PER_SM 3   // 72 regs x 256 thr -> 3 resident blocks/SM

// scratch for per-row projections (allocation-free rule: device globals)
__device__ float g_si[MAX_N];
__device__ float g_sj[MAX_N];

// ---------------------------------------------------------------------------
// Kernel 1: si[n] = dot(s[n,:], W[0:384]), sj[n] = dot(s[n,:], W[384:768])
// One warp per row, float4-vectorized.
// ---------------------------------------------------------------------------
__global__ void precompute_sisj_kernel(const float* __restrict__ s,
                                       const float* __restrict__ W,
                                       int N) {
    int warp = (blockIdx.x * blockDim.x + threadIdx.x) >> 5;
    int lane = threadIdx.x & 31;
    if (warp >= N) return;
    const float4* s4  = (const float4*)(s + (size_t)warp * C_S);  // 96 float4
    const float4* wi4 = (const float4*)W;
    const float4* wj4 = (const float4*)(W + C_S);
    float ai = 0.f, aj = 0.f;
#pragma unroll
    for (int i = 0; i < 3; i++) {
        int k = lane + 32 * i;
        float4 v  = __ldg(s4 + k);
        float4 wi = __ldg(wi4 + k);
        float4 wj = __ldg(wj4 + k);
        ai += v.x * wi.x + v.y * wi.y + v.z * wi.z + v.w * wi.w;
        aj += v.x * wj.x + v.y * wj.y + v.z * wj.z + v.w * wj.w;
    }
#pragma unroll
    for (int off = 16; off; off >>= 1) {
        ai += __shfl_xor_sync(0xFFFFFFFFu, ai, off);
        aj += __shfl_xor_sync(0xFFFFFFFFu, aj, off);
    }
    if (lane == 0) {
        g_si[warp] = ai;
        g_sj[warp] = aj;
    }
}

// ---------------------------------------------------------------------------
// Kernel 2: persistent warps, CONTIGUOUS per-warp batch ranges (sequential
// 4KB-after-4KB streaming per warp for DRAM row-buffer locality), software-
// pipelined double buffer so LDG.128s stay outstanding through the
// shfl-reduction tail.
// ---------------------------------------------------------------------------
__device__ __forceinline__ void load_batch(const float4* __restrict__ z4,
                                           long long batch, int lane,
                                           float4 v[8]) {
    size_t row0 = (size_t)batch * 8 * (C_Z / 4);
#pragma unroll
    for (int i = 0; i < 8; i++)
        v[i] = __ldg(z4 + row0 + (size_t)i * (C_Z / 4) + lane);
}

__device__ __forceinline__ void process_batch(const float4 v[8], float4 wz,
                                              float b0, long long batch,
                                              int lane, int N,
                                              float* __restrict__ out) {
    float a0 = v[0].x * wz.x + v[0].y * wz.y + v[0].z * wz.z + v[0].w * wz.w;
    float a1 = v[1].x * wz.x + v[1].y * wz.y + v[1].z * wz.z + v[1].w * wz.w;
    float a2 = v[2].x * wz.x + v[2].y * wz.y + v[2].z * wz.z + v[2].w * wz.w;
    float a3 = v[3].x * wz.x + v[3].y * wz.y + v[3].z * wz.z + v[3].w * wz.w;
    float a4 = v[4].x * wz.x + v[4].y * wz.y + v[4].z * wz.z + v[4].w * wz.w;
    float a5 = v[5].x * wz.x + v[5].y * wz.y + v[5].z * wz.z + v[5].w * wz.w;
    float a6 = v[6].x * wz.x + v[6].y * wz.y + v[6].z * wz.z + v[6].w * wz.w;
    float a7 = v[7].x * wz.x + v[7].y * wz.y + v[7].z * wz.z + v[7].w * wz.w;

    // Select-and-exchange multi-value reduction (9 shfls total).
    bool s0b = (lane & 1);
    float t0 = s0b ? a1 : a0;
    float t1 = s0b ? a3 : a2;
    float t2 = s0b ? a5 : a4;
    float t3 = s0b ? a7 : a6;
    t0 += __shfl_xor_sync(0xFFFFFFFFu, s0b ? a0 : a1, 1);
    t1 += __shfl_xor_sync(0xFFFFFFFFu, s0b ? a2 : a3, 1);
    t2 += __shfl_xor_sync(0xFFFFFFFFu, s0b ? a4 : a5, 1);
    t3 += __shfl_xor_sync(0xFFFFFFFFu, s0b ? a6 : a7, 1);
    bool s1b = (lane & 2);
    float u0 = s1b ? t1 : t0;
    float u1 = s1b ? t3 : t2;
    u0 += __shfl_xor_sync(0xFFFFFFFFu, s1b ? t0 : t1, 2);
    u1 += __shfl_xor_sync(0xFFFFFFFFu, s1b ? t2 : t3, 2);
    bool s2b = (lane & 4);
    float r = s2b ? u1 : u0;
    r += __shfl_xor_sync(0xFFFFFFFFu, s2b ? u0 : u1, 4);
    r += __shfl_xor_sync(0xFFFFFFFFu, r, 8);
    r += __shfl_xor_sync(0xFFFFFFFFu, r, 16);
    // lane l holds full sum for row (l & 7)

    if (lane < 8) {
        long long base = batch * 8;
        int n  = (int)(base / N);
        int m0 = (int)(base - (long long)n * N);
        out[base + lane] = r + g_si[n] + b0 + g_sj[m0 + lane];
    }
}

__global__ __launch_bounds__(256) void contact_main_kernel(
    const float* __restrict__ z,
    const float* __restrict__ W,
    const float* __restrict__ bias,
    float* __restrict__ out,
    int N) {
    long long gwarp  = (blockIdx.x * blockDim.x + threadIdx.x) >> 5;
    int lane         = threadIdx.x & 31;
    long long nwarps = (long long)(gridDim.x * blockDim.x) >> 5;

    long long nb = ((long long)N * N) / 8;  // total batches
    // Contiguous range for this warp: sequential streaming.
    long long batch = gwarp * nb / nwarps;
    long long bend  = (gwarp + 1) * nb / nwarps;
    if (batch >= bend) return;

    const float4* wz4 = (const float4*)(W + 2 * C_S);
    float4 wz = __ldg(wz4 + lane);
    float b0  = __ldg(bias);
    const float4* z4 = (const float4*)z;

    float4 va[8], vb[8];
    load_batch(z4, batch, lane, va);

    for (;;) {
        long long nxt = batch + 1;
        if (nxt < bend) {
            load_batch(z4, nxt, lane, vb);                  // loads in flight...
            process_batch(va, wz, b0, batch, lane, N, out); // ...through tail
            batch = nxt;
            long long nxt2 = batch + 1;
            if (nxt2 < bend) {
                load_batch(z4, nxt2, lane, va);
                process_batch(vb, wz, b0, batch, lane, N, out);
                batch = nxt2;
            } else {
                process_batch(vb, wz, b0, batch, lane, N, out);
                break;
            }
        } else {
            process_batch(va, wz, b0, batch, lane, N, out);
            break;
        }
    }
}

extern "C" void kernel_launch(void* const* d_in, const int* in_sizes, int n_in,
                              void* d_out, int out_size) {
    const float* s    = (const float*)d_in[0];   // (1, N, 384)
    const float* z    = (const float*)d_in[1];   // (1, N, N, 128)
    const float* W    = (const float*)d_in[2];   // (1, 896)
    const float* bias = (const float*)d_in[3];   // (1,)
    float* out = (float*)d_out;                  // (1, N, N, 1)

    int N = in_sizes[0] / C_S;                   // B=1

    // Kernel 1: one warp per row
    {
        int warps = N;
        int threads = 256;
        int blocks = (warps * 32 + threads - 1) / threads;
        precompute_sisj_kernel<<<blocks, threads>>>(s, W, N);
    }

    // Kernel 2: one-wave persistent grid (3 blocks/SM at 72 regs)
    {
        int threads = 256;
        int blocks = NSM * MAIN_BLKS_PER_SM;
        contact_main_kernel<<<blocks, threads>>>(z, W, bias, out, N);
    }
}

// round 9
// speedup vs baseline: 1.0076x; 1.0076x over previous
#include <cuda_runtime.h>

#define C_S 384
#define C_Z 128
#define MAX_N 2048
#define NSM 148
#define MAIN_BLKS_PER_SM 3

// scratch for per-row projections (allocation-free rule: device globals)
__device__ float g_si[MAX_N];
__device__ float g_sj[MAX_N];

// ---------------------------------------------------------------------------
// Kernel 1: si[n] = dot(s[n,:], W[0:384]), sj[n] = dot(s[n,:], W[384:768])
// One warp per row, float4-vectorized.
// ---------------------------------------------------------------------------
__global__ void precompute_sisj_kernel(const float* __restrict__ s,
                                       const float* __restrict__ W,
                                       int N) {
    int warp = (blockIdx.x * blockDim.x + threadIdx.x) >> 5;
    int lane = threadIdx.x & 31;
    if (warp >= N) return;
    const float4* s4  = (const float4*)(s + (size_t)warp * C_S);  // 96 float4
    const float4* wi4 = (const float4*)W;
    const float4* wj4 = (const float4*)(W + C_S);
    float ai = 0.f, aj = 0.f;
#pragma unroll
    for (int i = 0; i < 3; i++) {
        int k = lane + 32 * i;
        float4 v  = __ldg(s4 + k);
        float4 wi = __ldg(wi4 + k);
        float4 wj = __ldg(wj4 + k);
        ai += v.x * wi.x + v.y * wi.y + v.z * wi.z + v.w * wi.w;
        aj += v.x * wj.x + v.y * wj.y + v.z * wj.z + v.w * wj.w;
    }
#pragma unroll
    for (int off = 16; off; off >>= 1) {
        ai += __shfl_xor_sync(0xFFFFFFFFu, ai, off);
        aj += __shfl_xor_sync(0xFFFFFFFFu, aj, off);
    }
    if (lane == 0) {
        g_si[warp] = ai;
        g_sj[warp] = aj;
    }
}

// ---------------------------------------------------------------------------
// Kernel 2: persistent warps, contiguous per-warp batch ranges (sequential
// 4KB-after-4KB streaming per warp for DRAM row locality). All index math
// in 32-bit int (nb=131072 fits easily); __launch_bounds__(256,3) pins
// residency at 3 blocks/SM so register pressure can't collapse occupancy.
// Software-pipelined double buffer keeps LDG.128s outstanding through the
// shfl-reduction tail.
// ---------------------------------------------------------------------------
__device__ __forceinline__ void load_batch(const float4* __restrict__ z4,
                                           int batch, int lane,
                                           float4 v[8]) {
    size_t row0 = (size_t)batch * (8 * (C_Z / 4));
#pragma unroll
    for (int i = 0; i < 8; i++)
        v[i] = __ldg(z4 + row0 + i * (C_Z / 4) + lane);
}

__device__ __forceinline__ void process_batch(const float4 v[8], float4 wz,
                                              float b0, int batch,
                                              int lane, int N,
                                              float* __restrict__ out) {
    float a0 = v[0].x * wz.x + v[0].y * wz.y + v[0].z * wz.z + v[0].w * wz.w;
    float a1 = v[1].x * wz.x + v[1].y * wz.y + v[1].z * wz.z + v[1].w * wz.w;
    float a2 = v[2].x * wz.x + v[2].y * wz.y + v[2].z * wz.z + v[2].w * wz.w;
    float a3 = v[3].x * wz.x + v[3].y * wz.y + v[3].z * wz.z + v[3].w * wz.w;
    float a4 = v[4].x * wz.x + v[4].y * wz.y + v[4].z * wz.z + v[4].w * wz.w;
    float a5 = v[5].x * wz.x + v[5].y * wz.y + v[5].z * wz.z + v[5].w * wz.w;
    float a6 = v[6].x * wz.x + v[6].y * wz.y + v[6].z * wz.z + v[6].w * wz.w;
    float a7 = v[7].x * wz.x + v[7].y * wz.y + v[7].z * wz.z + v[7].w * wz.w;

    // Select-and-exchange multi-value reduction (9 shfls total).
    bool s0b = (lane & 1);
    float t0 = s0b ? a1 : a0;
    float t1 = s0b ? a3 : a2;
    float t2 = s0b ? a5 : a4;
    float t3 = s0b ? a7 : a6;
    t0 += __shfl_xor_sync(0xFFFFFFFFu, s0b ? a0 : a1, 1);
    t1 += __shfl_xor_sync(0xFFFFFFFFu, s0b ? a2 : a3, 1);
    t2 += __shfl_xor_sync(0xFFFFFFFFu, s0b ? a4 : a5, 1);
    t3 += __shfl_xor_sync(0xFFFFFFFFu, s0b ? a6 : a7, 1);
    bool s1b = (lane & 2);
    float u0 = s1b ? t1 : t0;
    float u1 = s1b ? t3 : t2;
    u0 += __shfl_xor_sync(0xFFFFFFFFu, s1b ? t0 : t1, 2);
    u1 += __shfl_xor_sync(0xFFFFFFFFu, s1b ? t2 : t3, 2);
    bool s2b = (lane & 4);
    float r = s2b ? u1 : u0;
    r += __shfl_xor_sync(0xFFFFFFFFu, s2b ? u0 : u1, 4);
    r += __shfl_xor_sync(0xFFFFFFFFu, r, 8);
    r += __shfl_xor_sync(0xFFFFFFFFu, r, 16);
    // lane l holds full sum for row (l & 7)

    if (lane < 8) {
        int base = batch * 8;
        int n  = base / N;        // N is power-of-two (1024): compiles to shift
        int m0 = base - n * N;
        out[(size_t)base + lane] = r + g_si[n] + b0 + g_sj[m0 + lane];
    }
}

__global__ __launch_bounds__(256, MAIN_BLKS_PER_SM) void contact_main_kernel(
    const float* __restrict__ z,
    const float* __restrict__ W,
    const float* __restrict__ bias,
    float* __restrict__ out,
    int N) {
    int gwarp  = (blockIdx.x * blockDim.x + threadIdx.x) >> 5;
    int lane   = threadIdx.x & 31;
    int nwarps = (gridDim.x * blockDim.x) >> 5;

    int nb = (N * N) / 8;  // total batches (131072 for N=1024)
    // Contiguous range for this warp: sequential streaming.
    int batch = (int)((long long)gwarp * nb / nwarps);
    int bend  = (int)((long long)(gwarp + 1) * nb / nwarps);
    if (batch >= bend) return;

    const float4* wz4 = (const float4*)(W + 2 * C_S);
    float4 wz = __ldg(wz4 + lane);
    float b0  = __ldg(bias);
    const float4* z4 = (const float4*)z;

    float4 va[8], vb[8];
    load_batch(z4, batch, lane, va);

    for (;;) {
        int nxt = batch + 1;
        if (nxt < bend) {
            load_batch(z4, nxt, lane, vb);                  // loads in flight...
            process_batch(va, wz, b0, batch, lane, N, out); // ...through tail
            batch = nxt;
            int nxt2 = batch + 1;
            if (nxt2 < bend) {
                load_batch(z4, nxt2, lane, va);
                process_batch(vb, wz, b0, batch, lane, N, out);
                batch = nxt2;
            } else {
                process_batch(vb, wz, b0, batch, lane, N, out);
                break;
            }
        } else {
            process_batch(va, wz, b0, batch, lane, N, out);
            break;
        }
    }
}

extern "C" void kernel_launch(void* const* d_in, const int* in_sizes, int n_in,
                              void* d_out, int out_size) {
    const float* s    = (const float*)d_in[0];   // (1, N, 384)
    const float* z    = (const float*)d_in[1];   // (1, N, N, 128)
    const float* W    = (const float*)d_in[2];   // (1, 896)
    const float* bias = (const float*)d_in[3];   // (1,)
    float* out = (float*)d_out;                  // (1, N, N, 1)

    int N = in_sizes[0] / C_S;                   // B=1

    // Kernel 1: one warp per row
    {
        int warps = N;
        int threads = 256;
        int blocks = (warps * 32 + threads - 1) / threads;
        precompute_sisj_kernel<<<blocks, threads>>>(s, W, N);
    }

    // Kernel 2: one-wave persistent grid (3 blocks/SM pinned)
    {
        int threads = 256;
        int blocks = NSM * MAIN_BLKS_PER_SM;
        contact_main_kernel<<<blocks, threads>>>(z, W, bias, out, N);
    }
}

// round 10
// speedup vs baseline: 1.0967x; 1.0884x over previous
#include <cuda_runtime.h>

#define C_S 384
#define C_Z 128
#define MAX_N 2048
#define NSM 148
#define MAIN_BLKS_PER_SM 3   // 72 regs x 256 thr -> 3 resident blocks/SM

// scratch for per-row projections (allocation-free rule: device globals)
__device__ float g_si[MAX_N];
__device__ float g_sj[MAX_N];

// ---------------------------------------------------------------------------
// Kernel 1: si[n] = dot(s[n,:], W[0:384]), sj[n] = dot(s[n,:], W[384:768])
// One warp per row, float4-vectorized. Publishes results, fences, then
// signals dependent-launch so the main kernel can start overlapped (PDL).
// ---------------------------------------------------------------------------
__global__ void precompute_sisj_kernel(const float* __restrict__ s,
                                       const float* __restrict__ W,
                                       int N) {
    int warp = (blockIdx.x * blockDim.x + threadIdx.x) >> 5;
    int lane = threadIdx.x & 31;
    if (warp < N) {
        const float4* s4  = (const float4*)(s + (size_t)warp * C_S);  // 96 float4
        const float4* wi4 = (const float4*)W;
        const float4* wj4 = (const float4*)(W + C_S);
        float ai = 0.f, aj = 0.f;
#pragma unroll
        for (int i = 0; i < 3; i++) {
            int k = lane + 32 * i;
            float4 v  = __ldg(s4 + k);
            float4 wi = __ldg(wi4 + k);
            float4 wj = __ldg(wj4 + k);
            ai += v.x * wi.x + v.y * wi.y + v.z * wi.z + v.w * wi.w;
            aj += v.x * wj.x + v.y * wj.y + v.z * wj.z + v.w * wj.w;
        }
#pragma unroll
        for (int off = 16; off; off >>= 1) {
            ai += __shfl_xor_sync(0xFFFFFFFFu, ai, off);
            aj += __shfl_xor_sync(0xFFFFFFFFu, aj, off);
        }
        if (lane == 0) {
            g_si[warp] = ai;
            g_sj[warp] = aj;
        }
    }
    __threadfence();
    // Allow the dependent (main) kernel to begin; its griddepcontrol.wait
    // returns once every primary CTA has executed this (writes visible).
    asm volatile("griddepcontrol.launch_dependents;");
}

// ---------------------------------------------------------------------------
// Kernel 2: persistent warps, INTERLEAVED grid-stride batches (adjacent warps
// own adjacent 4KB chunks -> dense chip-wide instantaneous footprint; proven
// best in R4/R5/R7 vs contiguous ranges in R8/R9). Software-pipelined double
// buffer keeps 8x LDG.128 outstanding through the shfl-reduction tail.
// ---------------------------------------------------------------------------
__device__ __forceinline__ void load_batch(const float4* __restrict__ z4,
                                           long long batch, int lane,
                                           float4 v[8]) {
    size_t row0 = (size_t)batch * 8 * (C_Z / 4);
#pragma unroll
    for (int i = 0; i < 8; i++)
        v[i] = __ldg(z4 + row0 + (size_t)i * (C_Z / 4) + lane);
}

__device__ __forceinline__ void process_batch(const float4 v[8], float4 wz,
                                              float b0, long long batch,
                                              int lane, int N,
                                              float* __restrict__ out) {
    float a0 = v[0].x * wz.x + v[0].y * wz.y + v[0].z * wz.z + v[0].w * wz.w;
    float a1 = v[1].x * wz.x + v[1].y * wz.y + v[1].z * wz.z + v[1].w * wz.w;
    float a2 = v[2].x * wz.x + v[2].y * wz.y + v[2].z * wz.z + v[2].w * wz.w;
    float a3 = v[3].x * wz.x + v[3].y * wz.y + v[3].z * wz.z + v[3].w * wz.w;
    float a4 = v[4].x * wz.x + v[4].y * wz.y + v[4].z * wz.z + v[4].w * wz.w;
    float a5 = v[5].x * wz.x + v[5].y * wz.y + v[5].z * wz.z + v[5].w * wz.w;
    float a6 = v[6].x * wz.x + v[6].y * wz.y + v[6].z * wz.z + v[6].w * wz.w;
    float a7 = v[7].x * wz.x + v[7].y * wz.y + v[7].z * wz.z + v[7].w * wz.w;

    // Select-and-exchange multi-value reduction (9 shfls total).
    bool s0b = (lane & 1);
    float t0 = s0b ? a1 : a0;
    float t1 = s0b ? a3 : a2;
    float t2 = s0b ? a5 : a4;
    float t3 = s0b ? a7 : a6;
    t0 += __shfl_xor_sync(0xFFFFFFFFu, s0b ? a0 : a1, 1);
    t1 += __shfl_xor_sync(0xFFFFFFFFu, s0b ? a2 : a3, 1);
    t2 += __shfl_xor_sync(0xFFFFFFFFu, s0b ? a4 : a5, 1);
    t3 += __shfl_xor_sync(0xFFFFFFFFu, s0b ? a6 : a7, 1);
    bool s1b = (lane & 2);
    float u0 = s1b ? t1 : t0;
    float u1 = s1b ? t3 : t2;
    u0 += __shfl_xor_sync(0xFFFFFFFFu, s1b ? t0 : t1, 2);
    u1 += __shfl_xor_sync(0xFFFFFFFFu, s1b ? t2 : t3, 2);
    bool s2b = (lane & 4);
    float r = s2b ? u1 : u0;
    r += __shfl_xor_sync(0xFFFFFFFFu, s2b ? u0 : u1, 4);
    r += __shfl_xor_sync(0xFFFFFFFFu, r, 8);
    r += __shfl_xor_sync(0xFFFFFFFFu, r, 16);
    // lane l holds full sum for row (l & 7)

    if (lane < 8) {
        long long base = batch * 8;
        int n  = (int)(base / N);
        int m0 = (int)(base - (long long)n * N);
        out[base + lane] = r + g_si[n] + b0 + g_sj[m0 + lane];
    }
}

__global__ __launch_bounds__(256) void contact_main_kernel(
    const float* __restrict__ z,
    const float* __restrict__ W,
    const float* __restrict__ bias,
    float* __restrict__ out,
    int N) {
    int gwarp = (blockIdx.x * blockDim.x + threadIdx.x) >> 5;
    int lane  = threadIdx.x & 31;
    long long stride = (long long)(gridDim.x * blockDim.x) >> 5;  // total warps

    long long nb = ((long long)N * N) / 8;  // total batches
    long long batch = gwarp;

    const float4* wz4 = (const float4*)(W + 2 * C_S);
    float4 wz = __ldg(wz4 + lane);
    float b0  = __ldg(bias);
    const float4* z4 = (const float4*)z;

    float4 va[8], vb[8];
    bool have = (batch < nb);
    if (have) load_batch(z4, batch, lane, va);  // z-loads don't depend on primary

    // Wait for the precompute kernel's writes (PDL). Our first-batch loads
    // are already in flight while we wait.
    asm volatile("griddepcontrol.wait;");

    if (!have) return;

    for (;;) {
        long long nxt = batch + stride;
        if (nxt < nb) {
            load_batch(z4, nxt, lane, vb);                  // loads in flight...
            process_batch(va, wz, b0, batch, lane, N, out); // ...through tail
            batch = nxt;
            long long nxt2 = batch + stride;
            if (nxt2 < nb) {
                load_batch(z4, nxt2, lane, va);
                process_batch(vb, wz, b0, batch, lane, N, out);
                batch = nxt2;
            } else {
                process_batch(vb, wz, b0, batch, lane, N, out);
                break;
            }
        } else {
            process_batch(va, wz, b0, batch, lane, N, out);
            break;
        }
    }
}

extern "C" void kernel_launch(void* const* d_in, const int* in_sizes, int n_in,
                              void* d_out, int out_size) {
    const float* s    = (const float*)d_in[0];   // (1, N, 384)
    const float* z    = (const float*)d_in[1];   // (1, N, N, 128)
    const float* W    = (const float*)d_in[2];   // (1, 896)
    const float* bias = (const float*)d_in[3];   // (1,)
    float* out = (float*)d_out;                  // (1, N, N, 1)

    int N = in_sizes[0] / C_S;                   // B=1

    // Kernel 1: one warp per row
    {
        int warps = N;
        int threads = 256;
        int blocks = (warps * 32 + threads - 1) / threads;
        precompute_sisj_kernel<<<blocks, threads>>>(s, W, N);
    }

    // Kernel 2: one-wave persistent grid, launched with Programmatic Stream
    // Serialization so it overlaps the primary's tail (waits via
    // griddepcontrol.wait inside the kernel).
    {
        cudaLaunchConfig_t cfg = {};
        cfg.gridDim  = dim3(NSM * MAIN_BLKS_PER_SM, 1, 1);
        cfg.blockDim = dim3(256, 1, 1);
        cfg.dynamicSmemBytes = 0;
        cfg.stream = 0;
        cudaLaunchAttribute attr[1];
        attr[0].id = cudaLaunchAttributeProgrammaticStreamSerialization;
        attr[0].val.programmaticStreamSerializationAllowed = 1;
        cfg.attrs = attr;
        cfg.numAttrs = 1;
        cudaLaunchKernelEx(&cfg, contact_main_kernel, z, W, bias, out, N);
    }
}

// round 11
// speedup vs baseline: 1.0971x; 1.0004x over previous
#include <cuda_runtime.h>

#define C_S 384
#define C_Z 128
#define MAX_N 2048
#define NSM 148
#define MAIN_BLKS_PER_SM 8   // 256 thr (8 warps) x 8 = 64 warps/SM: full residency

// scratch for per-row projections (allocation-free rule: device globals)
__device__ float g_si[MAX_N];
__device__ float g_sj[MAX_N];

// ---------------------------------------------------------------------------
// Kernel 1: si[n] = dot(s[n,:], W[0:384]), sj[n] = dot(s[n,:], W[384:768])
// One warp per row, float4-vectorized (3x LDG.128 of s per lane).
// ---------------------------------------------------------------------------
__global__ void precompute_sisj_kernel(const float* __restrict__ s,
                                       const float* __restrict__ W,
                                       int N) {
    int warp = (blockIdx.x * blockDim.x + threadIdx.x) >> 5;
    int lane = threadIdx.x & 31;
    if (warp >= N) return;
    const float4* s4  = (const float4*)(s + (size_t)warp * C_S);  // 96 float4
    const float4* wi4 = (const float4*)W;
    const float4* wj4 = (const float4*)(W + C_S);
    float ai = 0.f, aj = 0.f;
#pragma unroll
    for (int i = 0; i < 3; i++) {
        int k = lane + 32 * i;
        float4 v  = __ldg(s4 + k);
        float4 wi = __ldg(wi4 + k);
        float4 wj = __ldg(wj4 + k);
        ai += v.x * wi.x + v.y * wi.y + v.z * wi.z + v.w * wi.w;
        aj += v.x * wj.x + v.y * wj.y + v.z * wj.z + v.w * wj.w;
    }
#pragma unroll
    for (int off = 16; off; off >>= 1) {
        ai += __shfl_xor_sync(0xFFFFFFFFu, ai, off);
        aj += __shfl_xor_sync(0xFFFFFFFFu, aj, off);
    }
    if (lane == 0) {
        g_si[warp] = ai;
        g_sj[warp] = aj;
    }
}

// ---------------------------------------------------------------------------
// Kernel 2 (R5 config — best measured: 80.6us @ 85.3% DRAM):
// persistent warps, INTERLEAVED grid-stride batches (adjacent warps own
// adjacent 4KB chunks -> dense chip-wide address window), software-pipelined
// double buffer so 8x LDG.128 stay outstanding through the shfl-reduction
// tail. 72 regs -> full 8-blocks/SM residency at 1184 blocks.
// ---------------------------------------------------------------------------
__device__ __forceinline__ void load_batch(const float4* __restrict__ z4,
                                           long long batch, int lane,
                                           float4 v[8]) {
    size_t row0 = (size_t)batch * 8 * (C_Z / 4);
#pragma unroll
    for (int i = 0; i < 8; i++)
        v[i] = __ldg(z4 + row0 + (size_t)i * (C_Z / 4) + lane);
}

__device__ __forceinline__ void process_batch(const float4 v[8], float4 wz,
                                              float b0, long long batch,
                                              int lane, int N,
                                              float* __restrict__ out) {
    float a0 = v[0].x * wz.x + v[0].y * wz.y + v[0].z * wz.z + v[0].w * wz.w;
    float a1 = v[1].x * wz.x + v[1].y * wz.y + v[1].z * wz.z + v[1].w * wz.w;
    float a2 = v[2].x * wz.x + v[2].y * wz.y + v[2].z * wz.z + v[2].w * wz.w;
    float a3 = v[3].x * wz.x + v[3].y * wz.y + v[3].z * wz.z + v[3].w * wz.w;
    float a4 = v[4].x * wz.x + v[4].y * wz.y + v[4].z * wz.z + v[4].w * wz.w;
    float a5 = v[5].x * wz.x + v[5].y * wz.y + v[5].z * wz.z + v[5].w * wz.w;
    float a6 = v[6].x * wz.x + v[6].y * wz.y + v[6].z * wz.z + v[6].w * wz.w;
    float a7 = v[7].x * wz.x + v[7].y * wz.y + v[7].z * wz.z + v[7].w * wz.w;

    // Select-and-exchange multi-value reduction (9 shfls total).
    bool s0b = (lane & 1);
    float t0 = s0b ? a1 : a0;
    float t1 = s0b ? a3 : a2;
    float t2 = s0b ? a5 : a4;
    float t3 = s0b ? a7 : a6;
    t0 += __shfl_xor_sync(0xFFFFFFFFu, s0b ? a0 : a1, 1);
    t1 += __shfl_xor_sync(0xFFFFFFFFu, s0b ? a2 : a3, 1);
    t2 += __shfl_xor_sync(0xFFFFFFFFu, s0b ? a4 : a5, 1);
    t3 += __shfl_xor_sync(0xFFFFFFFFu, s0b ? a6 : a7, 1);
    bool s1b = (lane & 2);
    float u0 = s1b ? t1 : t0;
    float u1 = s1b ? t3 : t2;
    u0 += __shfl_xor_sync(0xFFFFFFFFu, s1b ? t0 : t1, 2);
    u1 += __shfl_xor_sync(0xFFFFFFFFu, s1b ? t2 : t3, 2);
    bool s2b = (lane & 4);
    float r = s2b ? u1 : u0;
    r += __shfl_xor_sync(0xFFFFFFFFu, s2b ? u0 : u1, 4);
    r += __shfl_xor_sync(0xFFFFFFFFu, r, 8);
    r += __shfl_xor_sync(0xFFFFFFFFu, r, 16);
    // lane l holds full sum for row (l & 7)

    if (lane < 8) {
        long long base = batch * 8;
        int n  = (int)(base / N);
        int m0 = (int)(base - (long long)n * N);
        out[base + lane] = r + g_si[n] + b0 + g_sj[m0 + lane];
    }
}

__global__ __launch_bounds__(256) void contact_main_kernel(
    const float* __restrict__ z,
    const float* __restrict__ W,
    const float* __restrict__ bias,
    float* __restrict__ out,
    int N) {
    int gwarp = (blockIdx.x * blockDim.x + threadIdx.x) >> 5;
    int lane  = threadIdx.x & 31;
    long long stride = (long long)(gridDim.x * blockDim.x) >> 5;  // total warps

    long long nb = ((long long)N * N) / 8;  // total batches
    long long batch = gwarp;
    if (batch >= nb) return;

    const float4* wz4 = (const float4*)(W + 2 * C_S);
    float4 wz = __ldg(wz4 + lane);
    float b0  = __ldg(bias);
    const float4* z4 = (const float4*)z;

    float4 va[8], vb[8];
    load_batch(z4, batch, lane, va);

    for (;;) {
        long long nxt = batch + stride;
        if (nxt < nb) {
            load_batch(z4, nxt, lane, vb);                  // loads in flight...
            process_batch(va, wz, b0, batch, lane, N, out); // ...through tail
            batch = nxt;
            long long nxt2 = batch + stride;
            if (nxt2 < nb) {
                load_batch(z4, nxt2, lane, va);
                process_batch(vb, wz, b0, batch, lane, N, out);
                batch = nxt2;
            } else {
                process_batch(vb, wz, b0, batch, lane, N, out);
                break;
            }
        } else {
            process_batch(va, wz, b0, batch, lane, N, out);
            break;
        }
    }
}

extern "C" void kernel_launch(void* const* d_in, const int* in_sizes, int n_in,
                              void* d_out, int out_size) {
    const float* s    = (const float*)d_in[0];   // (1, N, 384)
    const float* z    = (const float*)d_in[1];   // (1, N, N, 128)
    const float* W    = (const float*)d_in[2];   // (1, 896)
    const float* bias = (const float*)d_in[3];   // (1,)
    float* out = (float*)d_out;                  // (1, N, N, 1)

    int N = in_sizes[0] / C_S;                   // B=1

    // Kernel 1: one warp per row
    {
        int warps = N;
        int threads = 256;
        int blocks = (warps * 32 + threads - 1) / threads;
        precompute_sisj_kernel<<<blocks, threads>>>(s, W, N);
    }

    // Kernel 2: full-residency persistent grid (8 blocks/SM, R5 config)
    {
        int threads = 256;
        int blocks = NSM * MAIN_BLKS_PER_SM;  // 1184
        contact_main_kernel<<<blocks, threads>>>(z, W, bias, out, N);
    }
}